// round 13
// baseline (speedup 1.0000x reference)
#include <cuda_runtime.h>

#define Bn 4
#define Nn 128
#define Cn 128
#define TFn 8
#define En 8192
#define NEGV (-1e9f)
#define EPB 16           // edges per block (8 warps = 4 pairs x 4 edges)

// ---------------- scratch (static device globals; no allocation) ----------------
__device__ float g_msgE[Bn*Nn*Nn*Cn];
__device__ float g_T1[Bn*Nn*Nn*TFn];          // te1 transposed: [b][dst][src][f]
__device__ float g_T2[Bn*Nn*Nn*TFn];          // te2 transposed: [b][dst][src][f]
__device__ float g_te3[Bn*Nn*Nn*TFn];         // te3 normal:     [b][src][dst][f]
__device__ float g_msg1[Bn*Nn*Cn];
__device__ float g_msg2[Bn*Nn*Cn];
__device__ float g_u1[Bn*Nn*Cn];
__device__ float g_t1[Bn*Nn*TFn];
__device__ float g_t2[Bn*Nn*TFn];
__device__ float g_t3[Bn*Nn*TFn];
__device__ float g_mgg[Bn*Cn];
__device__ float g_tg[Bn*TFn];
__device__ unsigned g_maxacc[Bn*Nn*Cn];
// edge grouping by source key g = b*128+j
__device__ int g_cnt[Bn*Nn];
__device__ int g_offs[Bn*Nn];
__device__ int g_elist[En];

// ---------------- helpers ----------------
__device__ __forceinline__ unsigned fmap(float f) {
    int i = __float_as_int(f);
    return (i >= 0) ? ((unsigned)i | 0x80000000u) : ~(unsigned)i;
}
__device__ __forceinline__ float funmap(unsigned u) {
    int i = (u & 0x80000000u) ? (int)(u & 0x7FFFFFFFu) : ~(int)u;
    return __int_as_float(i);
}
__device__ __forceinline__ float wredsum(float v) {
    #pragma unroll
    for (int o = 16; o; o >>= 1) v += __shfl_xor_sync(0xffffffffu, v, o);
    return v;
}
__device__ __forceinline__ float brsum(float v, float* sred, int t) {
    v = wredsum(v);
    if ((t & 31) == 0) sred[t >> 5] = v;
    __syncthreads();
    v = sred[0] + sred[1] + sred[2] + sred[3];
    __syncthreads();
    return v;
}
__device__ __forceinline__ void fma2(unsigned long long& acc,
                                     unsigned long long a, unsigned long long b) {
    asm("fma.rn.f32x2 %0, %1, %2, %0;" : "+l"(acc) : "l"(a), "l"(b));
}
__device__ __forceinline__ unsigned long long bcast2(float x) {
    unsigned long long r;
    asm("mov.b64 %0, {%1, %1};" : "=l"(r) : "f"(x));
    return r;
}
__device__ __forceinline__ float2 unpack2(unsigned long long v) {
    float2 r;
    asm("mov.b64 {%0, %1}, %2;" : "=f"(r.x), "=f"(r.y) : "l"(v));
    return r;
}

// cooperative W slice staging: 32 k-rows x 128 cols = 16KB, 256 threads
__device__ __forceinline__ void stageW(float (*sWst)[128], const float* __restrict__ W,
                                       int ks, int t) {
    #pragma unroll
    for (int j = 0; j < 4; j++) {
        int elem = j*1024 + t*4;
        int row = elem >> 7, col = elem & 127;
        *(float4*)&sWst[row][col] = *(const float4*)&W[(ks + row)*128 + col];
    }
}

// Column-split GEMM over one staged 32-k slice. Pair p of warps handles 4 rows x
// 128 cols; this warp does cols [h*64,h*64+64), lane owns 2 cols (f32x2 acc/row).
// Per 4-k chunk: 4 LDS.64 (W) + 4 broadcast LDS.128 (A) + 16 mov + 16 FFMA2.
#define GEMMSW(sWst, sBlk, p, h, acc, ks)                                          \
    _Pragma("unroll 8")                                                            \
    for (int k0 = 0; k0 < 32; k0 += 4) {                                           \
        unsigned long long w0 = *(const unsigned long long*)&sWst[k0+0][h*64 + lane*2]; \
        unsigned long long w1 = *(const unsigned long long*)&sWst[k0+1][h*64 + lane*2]; \
        unsigned long long w2 = *(const unsigned long long*)&sWst[k0+2][h*64 + lane*2]; \
        unsigned long long w3 = *(const unsigned long long*)&sWst[k0+3][h*64 + lane*2]; \
        _Pragma("unroll")                                                          \
        for (int r = 0; r < 4; r++) {                                              \
            float4 a = *(const float4*)&(sBlk)[(p)*4 + r][(ks) + k0];              \
            fma2(acc[r], bcast2(a.x), w0);                                         \
            fma2(acc[r], bcast2(a.y), w1);                                         \
            fma2(acc[r], bcast2(a.z), w2);                                         \
            fma2(acc[r], bcast2(a.w), w3);                                         \
        }                                                                          \
    }

// ---------------- K1a: init main path (msgE edge slots + maxacc) ----------------
#define A4 (Bn*Nn*Nn*TFn/4)
#define B4 (En*32)
#define C4 (Bn*Nn*Cn/4)
__global__ void k_init_main(const int* __restrict__ eidx) {
    int idx = blockIdx.x * 256 + threadIdx.x;
    if (idx < B4) {
        int e = idx >> 5, o = idx & 31;
        int sg = eidx[e], dg = eidx[En + e];
        int b = sg >> 7, s = sg & 127, d = dg & 127;
        const float4 z4 = {0.f, 0.f, 0.f, 0.f};
        ((float4*)g_msgE)[((b*Nn + s)*Nn + d)*32 + o] = z4;
    } else if (idx < B4 + C4) {
        unsigned m = fmap(NEGV);
        uint4 mv = {m, m, m, m};
        ((uint4*)g_maxacc)[idx - B4] = mv;
    }
}

// ---------------- K2: node & graph projections ----------------
__global__ void k_proj(const float* __restrict__ node, const float* __restrict__ graph,
                       const float* __restrict__ Wm1, const float* __restrict__ Wm2,
                       const float* __restrict__ Wu1,
                       const float* __restrict__ Wt1, const float* __restrict__ Wt2,
                       const float* __restrict__ Wt3,
                       const float* __restrict__ Wmg, const float* __restrict__ Wtg) {
    __shared__ float sx[128];
    int blk = blockIdx.x, t = threadIdx.x;
    if (blk < Bn*Nn) {
        sx[t] = node[blk*128 + t];
        __syncthreads();
        float a1 = 0.f, a2 = 0.f, a3 = 0.f;
        #pragma unroll 8
        for (int f = 0; f < 128; f++) {
            float x = sx[f];
            a1 += x * Wm1[f*128 + t];
            a2 += x * Wm2[f*128 + t];
            a3 += x * Wu1[f*128 + t];
        }
        g_msg1[blk*128 + t] = a1;
        g_msg2[blk*128 + t] = a2;
        g_u1[blk*128 + t]   = a3;
        if (t < 24) {
            int jj = t & 7;
            const float* W = (t < 8) ? Wt1 : ((t < 16) ? Wt2 : Wt3);
            float a = 0.f;
            #pragma unroll 8
            for (int f = 0; f < 128; f++) a += sx[f] * W[f*8 + jj];
            float* dstp = (t < 8) ? g_t1 : ((t < 16) ? g_t2 : g_t3);
            dstp[blk*8 + jj] = a;
        }
    } else {
        int g = blk - Bn*Nn;
        sx[t] = graph[g*128 + t];
        __syncthreads();
        float a = 0.f;
        #pragma unroll 8
        for (int f = 0; f < 128; f++) a += sx[f] * Wmg[f*128 + t];
        g_mgg[g*128 + t] = a;
        if (t < 8) {
            float bb = 0.f;
            #pragma unroll 8
            for (int f = 0; f < 128; f++) bb += sx[f] * Wtg[f*8 + t];
            g_tg[g*8 + t] = bb;
        }
    }
}

// ---------------- K2b: build edge groups (single block, 512 threads) ----------------
__global__ void k_group(const int* __restrict__ eidx) {
    __shared__ int scnt[512], soff[512], scur[512];
    int t = threadIdx.x;
    scnt[t] = 0;
    __syncthreads();
    #pragma unroll
    for (int r = 0; r < En/512; r++)
        atomicAdd(&scnt[eidx[r*512 + t]], 1);
    __syncthreads();
    soff[t] = scnt[t];
    __syncthreads();
    for (int d = 1; d < 512; d <<= 1) {
        int v = (t >= d) ? soff[t-d] : 0;
        __syncthreads();
        soff[t] += v;
        __syncthreads();
    }
    int excl = soff[t] - scnt[t];
    g_offs[t] = excl;
    g_cnt[t]  = scnt[t];
    scur[t] = excl;
    __syncthreads();
    #pragma unroll
    for (int r = 0; r < En/512; r++) {
        int e = r*512 + t;
        int pos = atomicAdd(&scur[eidx[e]], 1);
        g_elist[pos] = e;
    }
}

// ---------------- K3: main edge projection, W-staged col-split GEMM + scatter-add ----------------
__global__ void __launch_bounds__(256)
k_scatter(const float* __restrict__ eattr, const int* __restrict__ eidx,
          const float* __restrict__ Wme) {
    __shared__ __align__(16) float sA[EPB][128];
    __shared__ __align__(16) float sWst[32][128];
    int t = threadIdx.x, warp = t >> 5, lane = t & 31;
    int p = warp >> 1, h = warp & 1;
    int e0 = blockIdx.x * EPB;
    #pragma unroll
    for (int i = 0; i < 2; i++) {
        int r = warp*2 + i;
        *(float4*)&sA[r][lane*4] = *(const float4*)&eattr[(e0 + r)*128 + lane*4];
    }
    int posMain[4];
    #pragma unroll
    for (int r = 0; r < 4; r++) {
        int e = e0 + p*4 + r;
        int sg = eidx[e], dg = eidx[En + e];
        int b = sg >> 7, s = sg & 127, d = dg & 127;
        posMain[r] = (b*Nn + s)*Nn + d;
    }
    unsigned long long acc[4] = {};
    #pragma unroll
    for (int ks = 0; ks < 128; ks += 32) {
        __syncthreads();
        stageW(sWst, Wme, ks, t);
        __syncthreads();
        GEMMSW(sWst, sA, p, h, acc, ks)
    }
    #pragma unroll
    for (int r = 0; r < 4; r++) {
        float2 v = unpack2(acc[r]);
        float* dst = &g_msgE[posMain[r]*128 + h*64 + lane*2];
        atomicAdd(dst + 0, v.x);
        atomicAdd(dst + 1, v.y);
    }
}

// ---------------- K3b: te projections (tri stream) ----------------
__global__ void __launch_bounds__(256)
k_te(const float* __restrict__ eattr, const int* __restrict__ eidx,
     const float* __restrict__ Wte1, const float* __restrict__ Wte2,
     const float* __restrict__ Wte3) {
    __shared__ __align__(16) float sA[32][128];
    __shared__ __align__(16) float sW[128][32];
    int t = threadIdx.x, warp = t >> 5, lane = t & 31;
    #pragma unroll
    for (int r = 0; r < 3; r++) {
        int idx = r*256 + t;
        int m = idx >> 8, o = idx & 255;
        int k = o >> 1, cc = o & 1;
        const float* W = (m == 0) ? Wte1 : ((m == 1) ? Wte2 : Wte3);
        *(float4*)&sW[k][m*8 + cc*4] = *(const float4*)&W[k*8 + cc*4];
    }
    int e0 = blockIdx.x * 32 + warp * 4;
    int posMain[4], posT[4];
    #pragma unroll
    for (int i = 0; i < 4; i++) {
        int e = e0 + i;
        *(float4*)&sA[warp*4 + i][lane*4] = *(const float4*)&eattr[e*128 + lane*4];
        int sg = eidx[e], dg = eidx[En + e];
        int b = sg >> 7, s = sg & 127, d = dg & 127;
        posMain[i] = (b*Nn + s)*Nn + d;
        posT[i]    = (b*Nn + d)*Nn + s;
    }
    __syncthreads();
    if (lane < 24) {
        int m = lane >> 3, c = lane & 7;
        float acc2[4] = {};
        #pragma unroll 8
        for (int k = 0; k < 128; k++) {
            float w = sW[k][lane];
            acc2[0] += sA[warp*4 + 0][k] * w;
            acc2[1] += sA[warp*4 + 1][k] * w;
            acc2[2] += sA[warp*4 + 2][k] * w;
            acc2[3] += sA[warp*4 + 3][k] * w;
        }
        #pragma unroll
        for (int i = 0; i < 4; i++) {
            if (m == 0)      atomicAdd(&g_T1[posT[i]*8 + c], acc2[i]);
            else if (m == 1) atomicAdd(&g_T2[posT[i]*8 + c], acc2[i]);
            else             atomicAdd(&g_te3[posMain[i]*8 + c], acc2[i]);
        }
    }
}

// ---------------- K4: fused MPNN chain, W-staged col-split GEMMs ----------------
__global__ void __launch_bounds__(256)
k_mpnn(const int* __restrict__ eidx,
       const float* __restrict__ ln1s, const float* __restrict__ ln1o,
       const float* __restrict__ W1,
       const float* __restrict__ ln2s, const float* __restrict__ ln2o,
       const float* __restrict__ W2) {
    __shared__ __align__(16) float sY[EPB][128];
    __shared__ __align__(16) float sWst[32][128];
    __shared__ float ssum[4][4][2];
    __shared__ float svar[4][4][2];
    int t = threadIdx.x, warp = t >> 5, lane = t & 31;
    int p = warp >> 1, h = warp & 1;
    int e0 = blockIdx.x * EPB;
    // ---- stage 1: gather + LN1 + ReLU (each warp: 2 edges, full width) ----
    {
        float4 s1 = *(const float4*)&ln1s[lane*4];
        float4 o1 = *(const float4*)&ln1o[lane*4];
        #pragma unroll
        for (int i = 0; i < 2; i++) {
            int r = warp*2 + i, e = e0 + r;
            int sg = eidx[e], dg = eidx[En + e];
            int b = sg >> 7, s = sg & 127, d = dg & 127;
            float4 x  = *(const float4*)&g_msgE[((b*Nn + s)*Nn + d)*128 + lane*4];
            float4 m1 = *(const float4*)&g_msg1[(b*Nn + d)*128 + lane*4];
            float4 m2 = *(const float4*)&g_msg2[(b*Nn + s)*128 + lane*4];
            float4 mg = *(const float4*)&g_mgg[b*128 + lane*4];
            x.x += m1.x + m2.x + mg.x;
            x.y += m1.y + m2.y + mg.y;
            x.z += m1.z + m2.z + mg.z;
            x.w += m1.w + m2.w + mg.w;
            float mean = wredsum(x.x + x.y + x.z + x.w) * (1.f/128.f);
            float dx = x.x - mean, dy = x.y - mean, dz = x.z - mean, dw = x.w - mean;
            float var = wredsum(dx*dx + dy*dy + dz*dz + dw*dw) * (1.f/128.f);
            float rstd = rsqrtf(var + 1e-5f);
            float4 y;
            y.x = fmaxf(s1.x * dx * rstd + o1.x, 0.f);
            y.y = fmaxf(s1.y * dy * rstd + o1.y, 0.f);
            y.z = fmaxf(s1.z * dz * rstd + o1.z, 0.f);
            y.w = fmaxf(s1.w * dw * rstd + o1.w, 0.f);
            *(float4*)&sY[r][lane*4] = y;
        }
    }
    int dglob[4];
    #pragma unroll
    for (int r = 0; r < 4; r++) {
        int e = e0 + p*4 + r;
        int sg = eidx[e], dg = eidx[En + e];
        dglob[r] = (sg >> 7)*Nn + (dg & 127);
    }
    // ---- stage 2: GEMM1 (W-staged) + cross-warp LN2 + ReLU ----
    {
        unsigned long long acc[4] = {};
        #pragma unroll
        for (int ks = 0; ks < 128; ks += 32) {
            __syncthreads();
            stageW(sWst, W1, ks, t);
            __syncthreads();
            GEMMSW(sWst, sY, p, h, acc, ks)
        }
        float2 vv[4];
        #pragma unroll
        for (int r = 0; r < 4; r++) {
            vv[r] = unpack2(acc[r]);
            float part = wredsum(vv[r].x + vv[r].y);
            if (lane == 0) ssum[p][r][h] = part;
        }
        __syncthreads();
        float mean[4];
        #pragma unroll
        for (int r = 0; r < 4; r++) {
            mean[r] = (ssum[p][r][0] + ssum[p][r][1]) * (1.f/128.f);
            float dx = vv[r].x - mean[r], dy = vv[r].y - mean[r];
            float part = wredsum(dx*dx + dy*dy);
            if (lane == 0) svar[p][r][h] = part;
        }
        __syncthreads();
        float2 s2 = *(const float2*)&ln2s[h*64 + lane*2];
        float2 o2 = *(const float2*)&ln2o[h*64 + lane*2];
        #pragma unroll
        for (int r = 0; r < 4; r++) {
            float var = (svar[p][r][0] + svar[p][r][1]) * (1.f/128.f);
            float rstd = rsqrtf(var + 1e-5f);
            float2 y;
            y.x = fmaxf(s2.x * (vv[r].x - mean[r]) * rstd + o2.x, 0.f);
            y.y = fmaxf(s2.y * (vv[r].y - mean[r]) * rstd + o2.y, 0.f);
            *(float2*)&sY[p*4 + r][h*64 + lane*2] = y;
        }
    }
    // ---- stage 3: GEMM2 (W-staged) + atomicMax ----
    {
        unsigned long long acc[4] = {};
        #pragma unroll
        for (int ks = 0; ks < 128; ks += 32) {
            __syncthreads();
            stageW(sWst, W2, ks, t);
            __syncthreads();
            GEMMSW(sWst, sY, p, h, acc, ks)
        }
        #pragma unroll
        for (int r = 0; r < 4; r++) {
            float2 v = unpack2(acc[r]);
            unsigned* dst = &g_maxacc[dglob[r]*128 + h*64 + lane*2];
            atomicMax(dst + 0, fmap(v.x));
            atomicMax(dst + 1, fmap(v.y));
        }
    }
}

// ---------------- K5: grouped triplet kernel, warp-per-edge (R9 form) ----------------
__global__ void __launch_bounds__(256)
k_tri2(const int* __restrict__ eidx, const float* __restrict__ Wu3,
       float* __restrict__ out2) {
    __shared__ __align__(16) float sX[128][8];
    __shared__ __align__(16) float sW[8*128];
    __shared__ float sbase[8];
    int g = blockIdx.x;
    int cnt = g_cnt[g];
    if (cnt == 0) return;
    int off = g_offs[g];
    int t = threadIdx.x, warp = t >> 5, lane = t & 31;
    int b = g >> 7;
    if (t < 128) {
        float4 a0 = ((const float4*)g_t1)[(b*128 + t)*2];
        float4 a1 = ((const float4*)g_t1)[(b*128 + t)*2 + 1];
        float4 b0 = ((const float4*)g_T1)[(g*128 + t)*2];
        float4 b1 = ((const float4*)g_T1)[(g*128 + t)*2 + 1];
        float4 x0 = {a0.x+b0.x, a0.y+b0.y, a0.z+b0.z, a0.w+b0.w};
        float4 x1 = {a1.x+b1.x, a1.y+b1.y, a1.z+b1.z, a1.w+b1.w};
        *(float4*)&sX[t][0] = x0;
        *(float4*)&sX[t][4] = x1;
    }
    ((float4*)sW)[t] = ((const float4*)Wu3)[t];
    if (t < 8) sbase[t] = g_t2[g*8 + t] + g_tg[b*8 + t];
    __syncthreads();
    float4 base0 = *(float4*)&sbase[0];
    float4 base1 = *(float4*)&sbase[4];
    const float4* T2v  = (const float4*)g_T2;
    const float4* t3v  = (const float4*)g_t3;
    const float4* te3v = (const float4*)g_te3;
    for (int n = warp; n < cnt; n += 8) {
        int e = g_elist[off + n];
        int k = eidx[En + e] & 127;
        float v[8];
        #pragma unroll
        for (int q = 0; q < 8; q++) v[q] = -3.0e38f;
        #pragma unroll
        for (int ii = 0; ii < 4; ii++) {
            int i = ii*32 + lane;
            float4 c0 = T2v[((b*128 + k)*128 + i)*2];
            float4 c1 = T2v[((b*128 + k)*128 + i)*2 + 1];
            float4 x0 = *(const float4*)&sX[i][0];
            float4 x1 = *(const float4*)&sX[i][4];
            v[0] = fmaxf(v[0], x0.x + c0.x);
            v[1] = fmaxf(v[1], x0.y + c0.y);
            v[2] = fmaxf(v[2], x0.z + c0.z);
            v[3] = fmaxf(v[3], x0.w + c0.w);
            v[4] = fmaxf(v[4], x1.x + c1.x);
            v[5] = fmaxf(v[5], x1.y + c1.y);
            v[6] = fmaxf(v[6], x1.z + c1.z);
            v[7] = fmaxf(v[7], x1.w + c1.w);
        }
        #pragma unroll
        for (int o = 16; o; o >>= 1) {
            #pragma unroll
            for (int q = 0; q < 8; q++)
                v[q] = fmaxf(v[q], __shfl_xor_sync(0xffffffffu, v[q], o));
        }
        float4 t30 = t3v[(b*128 + k)*2],  t31 = t3v[(b*128 + k)*2 + 1];
        float4 e30 = te3v[(g*128 + k)*2], e31 = te3v[(g*128 + k)*2 + 1];
        float s[8];
        s[0] = v[0] + base0.x + t30.x + e30.x;
        s[1] = v[1] + base0.y + t30.y + e30.y;
        s[2] = v[2] + base0.z + t30.z + e30.z;
        s[3] = v[3] + base0.w + t30.w + e30.w;
        s[4] = v[4] + base1.x + t31.x + e31.x;
        s[5] = v[5] + base1.y + t31.y + e31.y;
        s[6] = v[6] + base1.z + t31.z + e31.z;
        s[7] = v[7] + base1.w + t31.w + e31.w;
        float4 acc = {0.f, 0.f, 0.f, 0.f};
        #pragma unroll
        for (int f = 0; f < 8; f++) {
            float4 w = *(const float4*)&sW[f*128 + lane*4];
            acc.x += s[f]*w.x;
            acc.y += s[f]*w.y;
            acc.z += s[f]*w.z;
            acc.w += s[f]*w.w;
        }
        acc.x = fmaxf(acc.x, 0.f);
        acc.y = fmaxf(acc.y, 0.f);
        acc.z = fmaxf(acc.z, 0.f);
        acc.w = fmaxf(acc.w, 0.f);
        *(float4*)&out2[e*128 + lane*4] = acc;
    }
}

// ---------------- K6: final ret = LN(u1 + max @ W_u2) ----------------
__global__ void k_final(const float* __restrict__ Wu2,
                        const float* __restrict__ lnfs, const float* __restrict__ lnfo,
                        float* __restrict__ out1) {
    __shared__ float sm[128];
    __shared__ float sred[4];
    int n = blockIdx.x, t = threadIdx.x;
    sm[t] = funmap(g_maxacc[n*128 + t]);
    __syncthreads();
    float acc = g_u1[n*128 + t];
    #pragma unroll 8
    for (int f = 0; f < 128; f++) acc += sm[f] * Wu2[f*128 + t];
    float mean = brsum(acc, sred, t) * (1.f/128.f);
    float dmu = acc - mean;
    float var = brsum(dmu*dmu, sred, t) * (1.f/128.f);
    out1[n*128 + t] = lnfs[t] * dmu * rsqrtf(var + 1e-5f) + lnfo[t];
}

// ---------------- launch (multi-stream fork/join inside capture) ----------------
extern "C" void kernel_launch(void* const* d_in, const int* in_sizes, int n_in,
                              void* d_out, int out_size) {
    const float* node_fts  = (const float*)d_in[0];
    const float* edge_attr = (const float*)d_in[1];
    const float* graph_fts = (const float*)d_in[2];
    const float* W_tri1 = (const float*)d_in[3];
    const float* W_tri2 = (const float*)d_in[4];
    const float* W_tri3 = (const float*)d_in[5];
    const float* W_te1  = (const float*)d_in[6];
    const float* W_te2  = (const float*)d_in[7];
    const float* W_te3  = (const float*)d_in[8];
    const float* W_tg   = (const float*)d_in[9];
    const float* W_m1   = (const float*)d_in[10];
    const float* W_m2   = (const float*)d_in[11];
    const float* W_me   = (const float*)d_in[12];
    const float* W_mg   = (const float*)d_in[13];
    const float* ln1_s  = (const float*)d_in[14];
    const float* ln1_o  = (const float*)d_in[15];
    const float* W_mlp1 = (const float*)d_in[16];
    const float* ln2_s  = (const float*)d_in[17];
    const float* ln2_o  = (const float*)d_in[18];
    const float* W_mlp2 = (const float*)d_in[19];
    const float* W_u1   = (const float*)d_in[20];
    const float* W_u2   = (const float*)d_in[21];
    const float* W_u3   = (const float*)d_in[22];
    const float* lnf_s  = (const float*)d_in[23];
    const float* lnf_o  = (const float*)d_in[24];
    const int*   eidx   = (const int*)d_in[25];

    float* out1 = (float*)d_out;                 // ret      [512,128]
    float* out2 = out1 + Bn*Nn*Cn;               // tri gath [8192,128]

    static cudaStream_t s2 = 0, s3 = 0;
    static cudaEvent_t eFork = 0, eProj = 0, eTri = 0;
    static void *pT1 = 0, *pT2 = 0, *pte3 = 0;
    if (!s2) {
        cudaStreamCreateWithFlags(&s2, cudaStreamNonBlocking);
        cudaStreamCreateWithFlags(&s3, cudaStreamNonBlocking);
        cudaEventCreateWithFlags(&eFork, cudaEventDisableTiming);
        cudaEventCreateWithFlags(&eProj, cudaEventDisableTiming);
        cudaEventCreateWithFlags(&eTri,  cudaEventDisableTiming);
        cudaGetSymbolAddress(&pT1,  g_T1);
        cudaGetSymbolAddress(&pT2,  g_T2);
        cudaGetSymbolAddress(&pte3, g_te3);
    }

    // fork
    cudaEventRecord(eFork, 0);
    cudaStreamWaitEvent(s2, eFork, 0);
    cudaStreamWaitEvent(s3, eFork, 0);

    // s2: projections (independent)
    k_proj<<<Bn*Nn + Bn, 128, 0, s2>>>(node_fts, graph_fts, W_m1, W_m2, W_u1,
                                       W_tri1, W_tri2, W_tri3, W_mg, W_tg);
    cudaEventRecord(eProj, s2);

    // s3: independent triplet chain: memset te -> group -> te -> (proj) -> tri2
    cudaMemsetAsync(pT1,  0, sizeof(float)*Bn*Nn*Nn*TFn, s3);
    cudaMemsetAsync(pT2,  0, sizeof(float)*Bn*Nn*Nn*TFn, s3);
    cudaMemsetAsync(pte3, 0, sizeof(float)*Bn*Nn*Nn*TFn, s3);
    k_group<<<1, 512, 0, s3>>>(eidx);
    k_te<<<En/32, 256, 0, s3>>>(edge_attr, eidx, W_te1, W_te2, W_te3);
    cudaStreamWaitEvent(s3, eProj, 0);
    k_tri2<<<Bn*Nn, 256, 0, s3>>>(eidx, W_u3, out2);
    cudaEventRecord(eTri, s3);

    // main: init_main -> scatter -> (proj) -> mpnn -> final
    k_init_main<<<(B4 + C4 + 255)/256, 256>>>(eidx);
    k_scatter<<<En/EPB, 256>>>(edge_attr, eidx, W_me);
    cudaStreamWaitEvent(0, eProj, 0);
    k_mpnn<<<En/EPB, 256>>>(eidx, ln1_s, ln1_o, W_mlp1, ln2_s, ln2_o, W_mlp2);
    k_final<<<Bn*Nn, 128>>>(W_u2, lnf_s, lnf_o, out1);

    // join
    cudaStreamWaitEvent(0, eTri, 0);
}

// round 14
// speedup vs baseline: 1.2946x; 1.2946x over previous
#include <cuda_runtime.h>

#define Bn 4
#define Nn 128
#define Cn 128
#define TFn 8
#define En 8192
#define NEGV (-1e9f)
#define EPB 16           // edges per block (8 warps = 4 pairs x 4 edges)

// ---------------- scratch (static device globals; no allocation) ----------------
__device__ float g_msgE[Bn*Nn*Nn*Cn];
__device__ float g_T1[Bn*Nn*Nn*TFn];          // te1 transposed: [b][dst][src][f]
__device__ float g_T2[Bn*Nn*Nn*TFn];          // te2 transposed: [b][dst][src][f]
__device__ float g_te3[Bn*Nn*Nn*TFn];         // te3 normal:     [b][src][dst][f]
__device__ float g_msg1[Bn*Nn*Cn];
__device__ float g_msg2[Bn*Nn*Cn];
__device__ float g_u1[Bn*Nn*Cn];
__device__ float g_t1[Bn*Nn*TFn];
__device__ float g_t2[Bn*Nn*TFn];
__device__ float g_t3[Bn*Nn*TFn];
__device__ float g_mgg[Bn*Cn];
__device__ float g_tg[Bn*TFn];
__device__ unsigned g_maxacc[Bn*Nn*Cn];
// edge grouping by source key g = b*128+j
__device__ int g_cnt[Bn*Nn];
__device__ int g_offs[Bn*Nn];
__device__ int g_elist[En];

// ---------------- helpers ----------------
__device__ __forceinline__ unsigned fmap(float f) {
    int i = __float_as_int(f);
    return (i >= 0) ? ((unsigned)i | 0x80000000u) : ~(unsigned)i;
}
__device__ __forceinline__ float funmap(unsigned u) {
    int i = (u & 0x80000000u) ? (int)(u & 0x7FFFFFFFu) : ~(int)u;
    return __int_as_float(i);
}
__device__ __forceinline__ float wredsum(float v) {
    #pragma unroll
    for (int o = 16; o; o >>= 1) v += __shfl_xor_sync(0xffffffffu, v, o);
    return v;
}
__device__ __forceinline__ float brsum(float v, float* sred, int t) {
    v = wredsum(v);
    if ((t & 31) == 0) sred[t >> 5] = v;
    __syncthreads();
    v = sred[0] + sred[1] + sred[2] + sred[3];
    __syncthreads();
    return v;
}
__device__ __forceinline__ void fma2(unsigned long long& acc,
                                     unsigned long long a, unsigned long long b) {
    asm("fma.rn.f32x2 %0, %1, %2, %0;" : "+l"(acc) : "l"(a), "l"(b));
}
__device__ __forceinline__ unsigned long long bcast2(float x) {
    unsigned long long r;
    asm("mov.b64 %0, {%1, %1};" : "=l"(r) : "f"(x));
    return r;
}
__device__ __forceinline__ float2 unpack2(unsigned long long v) {
    float2 r;
    asm("mov.b64 {%0, %1}, %2;" : "=f"(r.x), "=f"(r.y) : "l"(v));
    return r;
}

// Column-split GEMM: pair of warps handles 4 rows x 128 cols; this warp does
// cols [h*64, h*64+64), lane owns 2 cols (one f32x2 acc per row).
// Per 4-k chunk: 4 LDG.64 + 4 broadcast LDS.128 + 16 mov + 16 FFMA2.
#define GEMMCS(Wp, sBlk, p, h, acc)                                               \
    _Pragma("unroll 4")                                                           \
    for (int k0 = 0; k0 < 128; k0 += 4) {                                         \
        unsigned long long w0 = *(const unsigned long long*)&Wp[(k0+0)*128 + h*64 + lane*2]; \
        unsigned long long w1 = *(const unsigned long long*)&Wp[(k0+1)*128 + h*64 + lane*2]; \
        unsigned long long w2 = *(const unsigned long long*)&Wp[(k0+2)*128 + h*64 + lane*2]; \
        unsigned long long w3 = *(const unsigned long long*)&Wp[(k0+3)*128 + h*64 + lane*2]; \
        _Pragma("unroll")                                                         \
        for (int r = 0; r < 4; r++) {                                             \
            float4 a = *(const float4*)&(sBlk)[(p)*4 + r][k0];                    \
            fma2(acc[r], bcast2(a.x), w0);                                        \
            fma2(acc[r], bcast2(a.y), w1);                                        \
            fma2(acc[r], bcast2(a.z), w2);                                        \
            fma2(acc[r], bcast2(a.w), w3);                                        \
        }                                                                         \
    }

// ---------------- K1a: zero msgE edge slots (critical path) ----------------
#define A4 (Bn*Nn*Nn*TFn/4)
#define B4 (En*32)
#define C4 (Bn*Nn*Cn/4)
__global__ void k_init_msgE(const int* __restrict__ eidx) {
    int idx = blockIdx.x * 256 + threadIdx.x;
    if (idx < B4) {
        int e = idx >> 5, o = idx & 31;
        int sg = eidx[e], dg = eidx[En + e];
        int b = sg >> 7, s = sg & 127, d = dg & 127;
        const float4 z4 = {0.f, 0.f, 0.f, 0.f};
        ((float4*)g_msgE)[((b*Nn + s)*Nn + d)*32 + o] = z4;
    }
}

// ---------------- K1b: init maxacc (s2, off critical path) ----------------
__global__ void k_init_max() {
    int idx = blockIdx.x * 256 + threadIdx.x;
    if (idx < C4) {
        unsigned m = fmap(NEGV);
        uint4 mv = {m, m, m, m};
        ((uint4*)g_maxacc)[idx] = mv;
    }
}

// ---------------- K2: node & graph projections ----------------
__global__ void k_proj(const float* __restrict__ node, const float* __restrict__ graph,
                       const float* __restrict__ Wm1, const float* __restrict__ Wm2,
                       const float* __restrict__ Wu1,
                       const float* __restrict__ Wt1, const float* __restrict__ Wt2,
                       const float* __restrict__ Wt3,
                       const float* __restrict__ Wmg, const float* __restrict__ Wtg) {
    __shared__ float sx[128];
    int blk = blockIdx.x, t = threadIdx.x;
    if (blk < Bn*Nn) {
        sx[t] = node[blk*128 + t];
        __syncthreads();
        float a1 = 0.f, a2 = 0.f, a3 = 0.f;
        #pragma unroll 8
        for (int f = 0; f < 128; f++) {
            float x = sx[f];
            a1 += x * Wm1[f*128 + t];
            a2 += x * Wm2[f*128 + t];
            a3 += x * Wu1[f*128 + t];
        }
        g_msg1[blk*128 + t] = a1;
        g_msg2[blk*128 + t] = a2;
        g_u1[blk*128 + t]   = a3;
        if (t < 24) {
            int jj = t & 7;
            const float* W = (t < 8) ? Wt1 : ((t < 16) ? Wt2 : Wt3);
            float a = 0.f;
            #pragma unroll 8
            for (int f = 0; f < 128; f++) a += sx[f] * W[f*8 + jj];
            float* dstp = (t < 8) ? g_t1 : ((t < 16) ? g_t2 : g_t3);
            dstp[blk*8 + jj] = a;
        }
    } else {
        int g = blk - Bn*Nn;
        sx[t] = graph[g*128 + t];
        __syncthreads();
        float a = 0.f;
        #pragma unroll 8
        for (int f = 0; f < 128; f++) a += sx[f] * Wmg[f*128 + t];
        g_mgg[g*128 + t] = a;
        if (t < 8) {
            float bb = 0.f;
            #pragma unroll 8
            for (int f = 0; f < 128; f++) bb += sx[f] * Wtg[f*8 + t];
            g_tg[g*8 + t] = bb;
        }
    }
}

// ---------------- K2b: build edge groups (single block, 512 threads) ----------------
__global__ void k_group(const int* __restrict__ eidx) {
    __shared__ int scnt[512], soff[512], scur[512];
    int t = threadIdx.x;
    scnt[t] = 0;
    __syncthreads();
    #pragma unroll
    for (int r = 0; r < En/512; r++)
        atomicAdd(&scnt[eidx[r*512 + t]], 1);
    __syncthreads();
    soff[t] = scnt[t];
    __syncthreads();
    for (int d = 1; d < 512; d <<= 1) {
        int v = (t >= d) ? soff[t-d] : 0;
        __syncthreads();
        soff[t] += v;
        __syncthreads();
    }
    int excl = soff[t] - scnt[t];
    g_offs[t] = excl;
    g_cnt[t]  = scnt[t];
    scur[t] = excl;
    __syncthreads();
    #pragma unroll
    for (int r = 0; r < En/512; r++) {
        int e = r*512 + t;
        int pos = atomicAdd(&scur[eidx[e]], 1);
        g_elist[pos] = e;
    }
}

// ---------------- K3: main edge projection, column-split GEMM + scatter-add ----------------
__global__ void __launch_bounds__(256)
k_scatter(const float* __restrict__ eattr, const int* __restrict__ eidx,
          const float* __restrict__ Wme) {
    __shared__ __align__(16) float sA[EPB][128];
    int t = threadIdx.x, warp = t >> 5, lane = t & 31;
    int p = warp >> 1, h = warp & 1;
    int e0 = blockIdx.x * EPB;
    #pragma unroll
    for (int i = 0; i < 2; i++) {
        int r = warp*2 + i;
        *(float4*)&sA[r][lane*4] = *(const float4*)&eattr[(e0 + r)*128 + lane*4];
    }
    int posMain[4];
    #pragma unroll
    for (int r = 0; r < 4; r++) {
        int e = e0 + p*4 + r;
        int sg = eidx[e], dg = eidx[En + e];
        int b = sg >> 7, s = sg & 127, d = dg & 127;
        posMain[r] = (b*Nn + s)*Nn + d;
    }
    __syncthreads();
    unsigned long long acc[4] = {};
    GEMMCS(Wme, sA, p, h, acc)
    #pragma unroll
    for (int r = 0; r < 4; r++) {
        float2 v = unpack2(acc[r]);
        float* dst = &g_msgE[posMain[r]*128 + h*64 + lane*2];
        atomicAdd(dst + 0, v.x);
        atomicAdd(dst + 1, v.y);
    }
}

// ---------------- K3b: te projections (tri stream) ----------------
__global__ void __launch_bounds__(256)
k_te(const float* __restrict__ eattr, const int* __restrict__ eidx,
     const float* __restrict__ Wte1, const float* __restrict__ Wte2,
     const float* __restrict__ Wte3) {
    __shared__ __align__(16) float sA[32][128];
    __shared__ __align__(16) float sW[128][32];
    int t = threadIdx.x, warp = t >> 5, lane = t & 31;
    #pragma unroll
    for (int r = 0; r < 3; r++) {
        int idx = r*256 + t;
        int m = idx >> 8, o = idx & 255;
        int k = o >> 1, cc = o & 1;
        const float* W = (m == 0) ? Wte1 : ((m == 1) ? Wte2 : Wte3);
        *(float4*)&sW[k][m*8 + cc*4] = *(const float4*)&W[k*8 + cc*4];
    }
    int e0 = blockIdx.x * 32 + warp * 4;
    int posMain[4], posT[4];
    #pragma unroll
    for (int i = 0; i < 4; i++) {
        int e = e0 + i;
        *(float4*)&sA[warp*4 + i][lane*4] = *(const float4*)&eattr[e*128 + lane*4];
        int sg = eidx[e], dg = eidx[En + e];
        int b = sg >> 7, s = sg & 127, d = dg & 127;
        posMain[i] = (b*Nn + s)*Nn + d;
        posT[i]    = (b*Nn + d)*Nn + s;
    }
    __syncthreads();
    if (lane < 24) {
        int m = lane >> 3, c = lane & 7;
        float acc2[4] = {};
        #pragma unroll 8
        for (int k = 0; k < 128; k++) {
            float w = sW[k][lane];
            acc2[0] += sA[warp*4 + 0][k] * w;
            acc2[1] += sA[warp*4 + 1][k] * w;
            acc2[2] += sA[warp*4 + 2][k] * w;
            acc2[3] += sA[warp*4 + 3][k] * w;
        }
        #pragma unroll
        for (int i = 0; i < 4; i++) {
            if (m == 0)      atomicAdd(&g_T1[posT[i]*8 + c], acc2[i]);
            else if (m == 1) atomicAdd(&g_T2[posT[i]*8 + c], acc2[i]);
            else             atomicAdd(&g_te3[posMain[i]*8 + c], acc2[i]);
        }
    }
}

// ---------------- K4: fused MPNN chain, column-split GEMMs ----------------
__global__ void __launch_bounds__(256)
k_mpnn(const int* __restrict__ eidx,
       const float* __restrict__ ln1s, const float* __restrict__ ln1o,
       const float* __restrict__ W1,
       const float* __restrict__ ln2s, const float* __restrict__ ln2o,
       const float* __restrict__ W2) {
    __shared__ __align__(16) float sY[EPB][128];
    __shared__ float ssum[4][4][2];
    __shared__ float svar[4][4][2];
    int t = threadIdx.x, warp = t >> 5, lane = t & 31;
    int p = warp >> 1, h = warp & 1;
    int e0 = blockIdx.x * EPB;
    // ---- stage 1: gather + LN1 + ReLU (each warp: 2 edges, full width) ----
    {
        float4 s1 = *(const float4*)&ln1s[lane*4];
        float4 o1 = *(const float4*)&ln1o[lane*4];
        #pragma unroll
        for (int i = 0; i < 2; i++) {
            int r = warp*2 + i, e = e0 + r;
            int sg = eidx[e], dg = eidx[En + e];
            int b = sg >> 7, s = sg & 127, d = dg & 127;
            float4 x  = *(const float4*)&g_msgE[((b*Nn + s)*Nn + d)*128 + lane*4];
            float4 m1 = *(const float4*)&g_msg1[(b*Nn + d)*128 + lane*4];
            float4 m2 = *(const float4*)&g_msg2[(b*Nn + s)*128 + lane*4];
            float4 mg = *(const float4*)&g_mgg[b*128 + lane*4];
            x.x += m1.x + m2.x + mg.x;
            x.y += m1.y + m2.y + mg.y;
            x.z += m1.z + m2.z + mg.z;
            x.w += m1.w + m2.w + mg.w;
            float mean = wredsum(x.x + x.y + x.z + x.w) * (1.f/128.f);
            float dx = x.x - mean, dy = x.y - mean, dz = x.z - mean, dw = x.w - mean;
            float var = wredsum(dx*dx + dy*dy + dz*dz + dw*dw) * (1.f/128.f);
            float rstd = rsqrtf(var + 1e-5f);
            float4 y;
            y.x = fmaxf(s1.x * dx * rstd + o1.x, 0.f);
            y.y = fmaxf(s1.y * dy * rstd + o1.y, 0.f);
            y.z = fmaxf(s1.z * dz * rstd + o1.z, 0.f);
            y.w = fmaxf(s1.w * dw * rstd + o1.w, 0.f);
            *(float4*)&sY[r][lane*4] = y;
        }
    }
    int dglob[4];
    #pragma unroll
    for (int r = 0; r < 4; r++) {
        int e = e0 + p*4 + r;
        int sg = eidx[e], dg = eidx[En + e];
        dglob[r] = (sg >> 7)*Nn + (dg & 127);
    }
    __syncthreads();
    // ---- stage 2: GEMM1 (col-split) + cross-warp LN2 + ReLU ----
    {
        unsigned long long acc[4] = {};
        GEMMCS(W1, sY, p, h, acc)
        float2 vv[4];
        #pragma unroll
        for (int r = 0; r < 4; r++) {
            vv[r] = unpack2(acc[r]);
            float part = wredsum(vv[r].x + vv[r].y);
            if (lane == 0) ssum[p][r][h] = part;
        }
        __syncthreads();
        float mean[4];
        #pragma unroll
        for (int r = 0; r < 4; r++) {
            mean[r] = (ssum[p][r][0] + ssum[p][r][1]) * (1.f/128.f);
            float dx = vv[r].x - mean[r], dy = vv[r].y - mean[r];
            float part = wredsum(dx*dx + dy*dy);
            if (lane == 0) svar[p][r][h] = part;
        }
        __syncthreads();
        float2 s2 = *(const float2*)&ln2s[h*64 + lane*2];
        float2 o2 = *(const float2*)&ln2o[h*64 + lane*2];
        #pragma unroll
        for (int r = 0; r < 4; r++) {
            float var = (svar[p][r][0] + svar[p][r][1]) * (1.f/128.f);
            float rstd = rsqrtf(var + 1e-5f);
            float2 y;
            y.x = fmaxf(s2.x * (vv[r].x - mean[r]) * rstd + o2.x, 0.f);
            y.y = fmaxf(s2.y * (vv[r].y - mean[r]) * rstd + o2.y, 0.f);
            *(float2*)&sY[p*4 + r][h*64 + lane*2] = y;
        }
    }
    __syncthreads();
    // ---- stage 3: GEMM2 (col-split) + atomicMax ----
    {
        unsigned long long acc[4] = {};
        GEMMCS(W2, sY, p, h, acc)
        #pragma unroll
        for (int r = 0; r < 4; r++) {
            float2 v = unpack2(acc[r]);
            unsigned* dst = &g_maxacc[dglob[r]*128 + h*64 + lane*2];
            atomicMax(dst + 0, fmap(v.x));
            atomicMax(dst + 1, fmap(v.y));
        }
    }
}

// ---------------- K5: grouped triplet kernel, warp-per-edge ----------------
__global__ void __launch_bounds__(256)
k_tri2(const int* __restrict__ eidx, const float* __restrict__ Wu3,
       float* __restrict__ out2) {
    __shared__ __align__(16) float sX[128][8];
    __shared__ __align__(16) float sW[8*128];
    __shared__ float sbase[8];
    int g = blockIdx.x;
    int cnt = g_cnt[g];
    if (cnt == 0) return;
    int off = g_offs[g];
    int t = threadIdx.x, warp = t >> 5, lane = t & 31;
    int b = g >> 7;
    if (t < 128) {
        float4 a0 = ((const float4*)g_t1)[(b*128 + t)*2];
        float4 a1 = ((const float4*)g_t1)[(b*128 + t)*2 + 1];
        float4 b0 = ((const float4*)g_T1)[(g*128 + t)*2];
        float4 b1 = ((const float4*)g_T1)[(g*128 + t)*2 + 1];
        float4 x0 = {a0.x+b0.x, a0.y+b0.y, a0.z+b0.z, a0.w+b0.w};
        float4 x1 = {a1.x+b1.x, a1.y+b1.y, a1.z+b1.z, a1.w+b1.w};
        *(float4*)&sX[t][0] = x0;
        *(float4*)&sX[t][4] = x1;
    }
    ((float4*)sW)[t] = ((const float4*)Wu3)[t];
    if (t < 8) sbase[t] = g_t2[g*8 + t] + g_tg[b*8 + t];
    __syncthreads();
    float4 base0 = *(float4*)&sbase[0];
    float4 base1 = *(float4*)&sbase[4];
    const float4* T2v  = (const float4*)g_T2;
    const float4* t3v  = (const float4*)g_t3;
    const float4* te3v = (const float4*)g_te3;
    for (int n = warp; n < cnt; n += 8) {
        int e = g_elist[off + n];
        int k = eidx[En + e] & 127;
        float v[8];
        #pragma unroll
        for (int q = 0; q < 8; q++) v[q] = -3.0e38f;
        #pragma unroll
        for (int ii = 0; ii < 4; ii++) {
            int i = ii*32 + lane;
            float4 c0 = T2v[((b*128 + k)*128 + i)*2];
            float4 c1 = T2v[((b*128 + k)*128 + i)*2 + 1];
            float4 x0 = *(const float4*)&sX[i][0];
            float4 x1 = *(const float4*)&sX[i][4];
            v[0] = fmaxf(v[0], x0.x + c0.x);
            v[1] = fmaxf(v[1], x0.y + c0.y);
            v[2] = fmaxf(v[2], x0.z + c0.z);
            v[3] = fmaxf(v[3], x0.w + c0.w);
            v[4] = fmaxf(v[4], x1.x + c1.x);
            v[5] = fmaxf(v[5], x1.y + c1.y);
            v[6] = fmaxf(v[6], x1.z + c1.z);
            v[7] = fmaxf(v[7], x1.w + c1.w);
        }
        #pragma unroll
        for (int o = 16; o; o >>= 1) {
            #pragma unroll
            for (int q = 0; q < 8; q++)
                v[q] = fmaxf(v[q], __shfl_xor_sync(0xffffffffu, v[q], o));
        }
        float4 t30 = t3v[(b*128 + k)*2],  t31 = t3v[(b*128 + k)*2 + 1];
        float4 e30 = te3v[(g*128 + k)*2], e31 = te3v[(g*128 + k)*2 + 1];
        float s[8];
        s[0] = v[0] + base0.x + t30.x + e30.x;
        s[1] = v[1] + base0.y + t30.y + e30.y;
        s[2] = v[2] + base0.z + t30.z + e30.z;
        s[3] = v[3] + base0.w + t30.w + e30.w;
        s[4] = v[4] + base1.x + t31.x + e31.x;
        s[5] = v[5] + base1.y + t31.y + e31.y;
        s[6] = v[6] + base1.z + t31.z + e31.z;
        s[7] = v[7] + base1.w + t31.w + e31.w;
        float4 acc = {0.f, 0.f, 0.f, 0.f};
        #pragma unroll
        for (int f = 0; f < 8; f++) {
            float4 w = *(const float4*)&sW[f*128 + lane*4];
            acc.x += s[f]*w.x;
            acc.y += s[f]*w.y;
            acc.z += s[f]*w.z;
            acc.w += s[f]*w.w;
        }
        acc.x = fmaxf(acc.x, 0.f);
        acc.y = fmaxf(acc.y, 0.f);
        acc.z = fmaxf(acc.z, 0.f);
        acc.w = fmaxf(acc.w, 0.f);
        *(float4*)&out2[e*128 + lane*4] = acc;
    }
}

// ---------------- K6: final ret = LN(u1 + max @ W_u2) ----------------
__global__ void k_final(const float* __restrict__ Wu2,
                        const float* __restrict__ lnfs, const float* __restrict__ lnfo,
                        float* __restrict__ out1) {
    __shared__ float sm[128];
    __shared__ float sred[4];
    int n = blockIdx.x, t = threadIdx.x;
    sm[t] = funmap(g_maxacc[n*128 + t]);
    __syncthreads();
    float acc = g_u1[n*128 + t];
    #pragma unroll 8
    for (int f = 0; f < 128; f++) acc += sm[f] * Wu2[f*128 + t];
    float mean = brsum(acc, sred, t) * (1.f/128.f);
    float dmu = acc - mean;
    float var = brsum(dmu*dmu, sred, t) * (1.f/128.f);
    out1[n*128 + t] = lnfs[t] * dmu * rsqrtf(var + 1e-5f) + lnfo[t];
}

// ---------------- launch (multi-stream fork/join inside capture) ----------------
extern "C" void kernel_launch(void* const* d_in, const int* in_sizes, int n_in,
                              void* d_out, int out_size) {
    const float* node_fts  = (const float*)d_in[0];
    const float* edge_attr = (const float*)d_in[1];
    const float* graph_fts = (const float*)d_in[2];
    const float* W_tri1 = (const float*)d_in[3];
    const float* W_tri2 = (const float*)d_in[4];
    const float* W_tri3 = (const float*)d_in[5];
    const float* W_te1  = (const float*)d_in[6];
    const float* W_te2  = (const float*)d_in[7];
    const float* W_te3  = (const float*)d_in[8];
    const float* W_tg   = (const float*)d_in[9];
    const float* W_m1   = (const float*)d_in[10];
    const float* W_m2   = (const float*)d_in[11];
    const float* W_me   = (const float*)d_in[12];
    const float* W_mg   = (const float*)d_in[13];
    const float* ln1_s  = (const float*)d_in[14];
    const float* ln1_o  = (const float*)d_in[15];
    const float* W_mlp1 = (const float*)d_in[16];
    const float* ln2_s  = (const float*)d_in[17];
    const float* ln2_o  = (const float*)d_in[18];
    const float* W_mlp2 = (const float*)d_in[19];
    const float* W_u1   = (const float*)d_in[20];
    const float* W_u2   = (const float*)d_in[21];
    const float* W_u3   = (const float*)d_in[22];
    const float* lnf_s  = (const float*)d_in[23];
    const float* lnf_o  = (const float*)d_in[24];
    const int*   eidx   = (const int*)d_in[25];

    float* out1 = (float*)d_out;                 // ret      [512,128]
    float* out2 = out1 + Bn*Nn*Cn;               // tri gath [8192,128]

    static cudaStream_t s2 = 0, s3 = 0;
    static cudaEvent_t eFork = 0, eProj = 0, eTri = 0;
    static void *pT1 = 0, *pT2 = 0, *pte3 = 0;
    if (!s2) {
        cudaStreamCreateWithFlags(&s2, cudaStreamNonBlocking);
        cudaStreamCreateWithFlags(&s3, cudaStreamNonBlocking);
        cudaEventCreateWithFlags(&eFork, cudaEventDisableTiming);
        cudaEventCreateWithFlags(&eProj, cudaEventDisableTiming);
        cudaEventCreateWithFlags(&eTri,  cudaEventDisableTiming);
        cudaGetSymbolAddress(&pT1,  g_T1);
        cudaGetSymbolAddress(&pT2,  g_T2);
        cudaGetSymbolAddress(&pte3, g_te3);
    }

    // fork
    cudaEventRecord(eFork, 0);
    cudaStreamWaitEvent(s2, eFork, 0);
    cudaStreamWaitEvent(s3, eFork, 0);

    // s2: projections + maxacc init (both needed only by k_mpnn / k_final)
    k_proj<<<Bn*Nn + Bn, 128, 0, s2>>>(node_fts, graph_fts, W_m1, W_m2, W_u1,
                                       W_tri1, W_tri2, W_tri3, W_mg, W_tg);
    k_init_max<<<(C4 + 255)/256, 256, 0, s2>>>();
    cudaEventRecord(eProj, s2);

    // s3: independent triplet chain: memset te -> group -> te -> (proj) -> tri2
    cudaMemsetAsync(pT1,  0, sizeof(float)*Bn*Nn*Nn*TFn, s3);
    cudaMemsetAsync(pT2,  0, sizeof(float)*Bn*Nn*Nn*TFn, s3);
    cudaMemsetAsync(pte3, 0, sizeof(float)*Bn*Nn*Nn*TFn, s3);
    k_group<<<1, 512, 0, s3>>>(eidx);
    k_te<<<En/32, 256, 0, s3>>>(edge_attr, eidx, W_te1, W_te2, W_te3);
    cudaStreamWaitEvent(s3, eProj, 0);
    k_tri2<<<Bn*Nn, 256, 0, s3>>>(eidx, W_u3, out2);
    cudaEventRecord(eTri, s3);

    // main: init_msgE -> scatter -> (proj+maxinit) -> mpnn -> final
    k_init_msgE<<<(B4 + 255)/256, 256>>>(eidx);
    k_scatter<<<En/EPB, 256>>>(edge_attr, eidx, W_me);
    cudaStreamWaitEvent(0, eProj, 0);
    k_mpnn<<<En/EPB, 256>>>(eidx, ln1_s, ln1_o, W_mlp1, ln2_s, ln2_o, W_mlp2);
    k_final<<<Bn*Nn, 128>>>(W_u2, lnf_s, lnf_o, out1);

    // join
    cudaStreamWaitEvent(0, eTri, 0);
}